// round 14
// baseline (speedup 1.0000x reference)
#include <cuda_runtime.h>
#include <cuda_bf16.h>
#include <cstdint>

#define N_TOK   32768
#define K_CODES 1024
#define D_DIM   256
#define BM      64

// Output layout: reference tuple concatenated as float32 in return order.
#define OFF_ZQ    0ull
#define OFF_CODES 8388608ull
#define OFF_LOSS  8421376ull
#define OFF_PERP  8421377ull
#define OFF_ENT   8421378ull
#define OFF_SA    8421379ull
#define OFF_EMBED 41975811ull
#define OFF_CS    42237955ull
#define OFF_EA    42238979ull

// ---------------------------------------------------------------------------
// Scratch (__device__ globals; no runtime allocation allowed)
__device__ float g_esum[K_CODES * D_DIM];
__device__ float g_counts[K_CODES];
__device__ float g_commit;
__device__ float g_ee[K_CODES];
__device__ float g_invcs[K_CODES];
__device__ __align__(16) unsigned short g_eh[K_CODES * D_DIM];  // embed bf16 hi
__device__ __align__(16) unsigned short g_el[K_CODES * D_DIM];  // embed bf16 lo

// ---------------------------------------------------------------------------
__device__ __forceinline__ uint32_t smem_u32(const void* p) {
    uint32_t a;
    asm("{ .reg .u64 t; cvta.to.shared.u64 t, %1; cvt.u32.u64 %0, t; }" : "=r"(a) : "l"(p));
    return a;
}
__device__ __forceinline__ float ex2(float x) {
    float r; asm("ex2.approx.ftz.f32 %0, %1;" : "=f"(r) : "f"(x)); return r;
}
#define SWZ(o) ((o) ^ (((o) >> 3) & 0x70u))

#define LDSM4(r, a) \
    asm volatile("ldmatrix.sync.aligned.m8n8.x4.shared.b16 {%0,%1,%2,%3}, [%4];" \
        : "=r"((r)[0]), "=r"((r)[1]), "=r"((r)[2]), "=r"((r)[3]) : "r"(a))
#define MMA16816(d, a, b) \
    asm volatile("mma.sync.aligned.m16n8k16.row.col.f32.bf16.bf16.f32 " \
        "{%0,%1,%2,%3},{%4,%5,%6,%7},{%8,%9},{%0,%1,%2,%3};" \
        : "+f"((d)[0]), "+f"((d)[1]), "+f"((d)[2]), "+f"((d)[3]) \
        : "r"((a)[0]), "r"((a)[1]), "r"((a)[2]), "r"((a)[3]), "r"((b)[0]), "r"((b)[1]))

#define CP_ASYNC16(saddr, gptr) \
    asm volatile("cp.async.cg.shared.global [%0], [%1], 16;" :: "r"(saddr), "l"(gptr))
#define CP_COMMIT() asm volatile("cp.async.commit_group;" ::: "memory")
#define CP_WAIT(n)  asm volatile("cp.async.wait_group %0;" :: "n"(n) : "memory")

__device__ __forceinline__ unsigned short f2bf(float v) {
    __nv_bfloat16 b = __float2bfloat16(v);
    return *reinterpret_cast<unsigned short*>(&b);
}
__device__ __forceinline__ float bf2f(unsigned short u) {
    __nv_bfloat16 b = *reinterpret_cast<__nv_bfloat16*>(&u);
    return __bfloat162float(b);
}

// ---------------------------------------------------------------------------
// embed prep: zero scratch + bf16 hi/lo split + squared norms. One warp/code.
__global__ void __launch_bounds__(256) embed_prep_kernel(const float* __restrict__ embed) {
    int gid = blockIdx.x * 256 + threadIdx.x;   // 0..32767
#pragma unroll
    for (int k = 0; k < 8; k++) g_esum[gid + k * 32768] = 0.f;
    if (gid < K_CODES) g_counts[gid] = 0.f;
    if (gid == 0) g_commit = 0.f;

    int w = threadIdx.x >> 5, lane = threadIdx.x & 31;
    int k = blockIdx.x * 8 + w;
    const float* e = embed + (size_t)k * D_DIM;
    float s = 0.f;
#pragma unroll
    for (int j = 0; j < 8; j++) {
        int d = lane + 32 * j;
        float v = e[d];
        unsigned short h = f2bf(v);
        unsigned short l = f2bf(v - bf2f(h));
        g_eh[k * D_DIM + d] = h;
        g_el[k * D_DIM + d] = l;
        s += v * v;
    }
#pragma unroll
    for (int o = 16; o; o >>= 1) s += __shfl_xor_sync(0xffffffffu, s, o);
    if (lane == 0) g_ee[k] = s;
}

// ---------------------------------------------------------------------------
// SMEM layout (bytes) — total 105088 -> 2 CTAs/SM
#define SM_RED  0u
#define SM_ZZ   64u
#define SM_PM   320u
#define SM_PS   832u
#define SM_PI   1344u
#define SM_FM   1856u
#define SM_FS   2112u
#define SM_FI   2368u
#define SM_EE   2624u
#define SM_Z    6784u
#define SM_E    72320u
#define SMEM_BYTES 105088u

// merge two online-softmax states
__device__ __forceinline__ void osm_merge(float& m, float& s, int& i,
                                          float om, float os, int oi, float C) {
    if (om < m || (om == m && oi < i)) {
        s = os + s * ex2((om - m) * C);
        m = om; i = oi;
    } else {
        s = s + os * ex2((m - om) * C);
    }
}

// async copy of E chunk L (nt = L>>2, c = L&3): 64 codes x 64 d, hi+lo = 16 KB
__device__ __forceinline__ void copy_chunk(uint32_t sb, int L, int tid) {
    int nt = L >> 2, c = L & 3;
    uint32_t dstb = SM_E + (uint32_t)(L & 1) * 16384u;
#pragma unroll
    for (int m = 0; m < 4; m++) {
        int linear = m * 256 + tid;          // 0..1023
        int s = linear >> 9, rem = linear & 511;
        int i = rem >> 3, grp = rem & 7;
        const unsigned short* src = s ? g_el : g_eh;
        const void* gp = (const void*)(src + ((size_t)(nt * 64 + i) * D_DIM + c * 64 + grp * 8));
        uint32_t off = SWZ((uint32_t)(i * 128 + grp * 16));
        CP_ASYNC16(sb + dstb + (uint32_t)s * 8192u + off, gp);
    }
}

// online-softmax update with negligible-term culling:
// terms with (m-d)*C < -40 contribute < 2^-40 to the sum -> skip the MUFU.
__device__ __forceinline__ void osm_upd(float& m, float& s, int& i,
                                        float d, int idx, float C) {
    if (d < m) {
        s = s * ex2((d - m) * C) + 1.f;
        m = d; i = idx;
    } else {
        float t = (m - d) * C;
        if (t > -40.f) s += ex2(t);
    }
}

__global__ void __launch_bounds__(256, 2) dist_kernel(
    const float* __restrict__ z, const float* __restrict__ embed,
    float* __restrict__ out)
{
    extern __shared__ char smem[];
    const uint32_t sb = smem_u32(smem);
    const int tid = threadIdx.x;
    const int w = tid >> 5, lane = tid & 31;
    const int wm = w & 3, wn = w >> 2;        // warp grid 4 (M) x 2 (N)
    const int brow = blockIdx.x * BM;
    const float C = 14.4269504088896341f;      // 10 / ln(2)

    float* red  = (float*)(smem + SM_RED);
    float* zz   = (float*)(smem + SM_ZZ);
    float* ee_s = (float*)(smem + SM_EE);
    float* pm   = (float*)(smem + SM_PM);
    float* ps   = (float*)(smem + SM_PS);
    int*   pi   = (int*)  (smem + SM_PI);
    float* fm   = (float*)(smem + SM_FM);
    float* fs   = (float*)(smem + SM_FS);
    int*   fi   = (int*)  (smem + SM_FI);

    if (tid < BM) zz[tid] = 0.f;
    __syncthreads();

    // kick off E chunk 0 fetch; overlaps z-tile load/split
    copy_chunk(sb, 0, tid);
    CP_COMMIT();

    // ---- load z tile [64 x 256] -> bf16 hi/lo split, swizzled smem, row norms
    {
        int r = tid >> 2, q = tid & 3;       // 4 threads per row, 64 d each
        float s = 0.f;
#pragma unroll
        for (int j = 0; j < 8; j++) {
            int d = q * 64 + j * 8;
            const float4* zp = (const float4*)(z + (size_t)(brow + r) * D_DIM + d);
            float4 a = zp[0], b = zp[1];
            float f[8] = {a.x, a.y, a.z, a.w, b.x, b.y, b.z, b.w};
            uint32_t hv[4], lv[4];
#pragma unroll
            for (int p = 0; p < 4; p++) {
                unsigned short h0 = f2bf(f[2*p]),   h1 = f2bf(f[2*p+1]);
                unsigned short l0 = f2bf(f[2*p]   - bf2f(h0));
                unsigned short l1 = f2bf(f[2*p+1] - bf2f(h1));
                hv[p] = (uint32_t)h0 | ((uint32_t)h1 << 16);
                lv[p] = (uint32_t)l0 | ((uint32_t)l1 << 16);
                s += f[2*p]*f[2*p] + f[2*p+1]*f[2*p+1];
            }
            int col = j * 8;
            uint32_t off = SWZ((uint32_t)(r * 128 + col * 2));
            *(uint4*)(smem + SM_Z + (0 + q) * 8192 + off) = make_uint4(hv[0],hv[1],hv[2],hv[3]);
            *(uint4*)(smem + SM_Z + (4 + q) * 8192 + off) = make_uint4(lv[0],lv[1],lv[2],lv[3]);
        }
        atomicAdd(&zz[r], s);
    }
    // preload ALL code norms once (1024 floats)
#pragma unroll
    for (int k = 0; k < 4; k++) ee_s[tid + k * 256] = g_ee[tid + k * 256];
    __syncthreads();

    const int g  = lane >> 2;           // fragment row-in-8
    const int t2 = (lane & 3) * 2;      // fragment col pair
    float zzr[2];
    zzr[0] = zz[wm * 16 + g];
    zzr[1] = zz[wm * 16 + g + 8];

    // online softmax state per owned row-slot (rows wm*16+g, +8)
    float osm_m[2] = {3.4e38f, 3.4e38f};
    float osm_s[2] = {0.f, 0.f};
    int   osm_i[2] = {0, 0};

    for (int nt = 0; nt < 16; nt++) {
        float acc[4][4];
#pragma unroll
        for (int tn = 0; tn < 4; tn++)
#pragma unroll
            for (int q = 0; q < 4; q++) acc[tn][q] = 0.f;

        for (int c = 0; c < 4; c++) {
            const int L = nt * 4 + c;
            if (L + 1 < 64) {
                copy_chunk(sb, L + 1, tid);
                CP_COMMIT();
                CP_WAIT(1);          // chunk L complete, L+1 in flight
            } else {
                CP_WAIT(0);
            }
            __syncthreads();

            const uint32_t eb = SM_E + (uint32_t)(L & 1) * 16384u;
#pragma unroll
            for (int ks = 0; ks < 4; ks++) {
                uint32_t ah[4], al[4];
                {
                    int row = wm * 16 + (lane & 15);
                    uint32_t kg = (uint32_t)(ks * 2 + (lane >> 4));
                    uint32_t boff = (uint32_t)(row * 128) + ((kg ^ (row & 7)) << 4);
                    LDSM4(ah, sb + SM_Z + (0 + c) * 8192 + boff);
                    LDSM4(al, sb + SM_Z + (4 + c) * 8192 + boff);
                }
                uint32_t bh[4][2], bl[4][2];
#pragma unroll
                for (int jp = 0; jp < 2; jp++) {
                    int mi = lane >> 3;
                    int row = wn * 32 + (jp * 2 + (mi >> 1)) * 8 + (lane & 7);
                    uint32_t kg = (uint32_t)(ks * 2 + (mi & 1));
                    uint32_t boff = (uint32_t)(row * 128) + ((kg ^ (row & 7)) << 4);
                    uint32_t q[4];
                    LDSM4(q, sb + eb + boff);
                    bh[jp*2+0][0] = q[0]; bh[jp*2+0][1] = q[1];
                    bh[jp*2+1][0] = q[2]; bh[jp*2+1][1] = q[3];
                    LDSM4(q, sb + eb + 8192u + boff);
                    bl[jp*2+0][0] = q[0]; bl[jp*2+0][1] = q[1];
                    bl[jp*2+1][0] = q[2]; bl[jp*2+1][1] = q[3];
                }
#pragma unroll
                for (int j = 0; j < 4; j++) MMA16816(acc[j], ah, bh[j]);
#pragma unroll
                for (int j = 0; j < 4; j++) MMA16816(acc[j], ah, bl[j]);
#pragma unroll
                for (int j = 0; j < 4; j++) MMA16816(acc[j], al, bh[j]);
            }
            __syncthreads();
        }

        // ---- epilogue: dist, culled online softmax, scalar STG to sa slot
        int r0 = wm * 16 + g;
#pragma unroll
        for (int tn = 0; tn < 4; tn++) {
            int col = wn * 32 + tn * 8 + t2;
            int gc  = nt * 64 + col;
            float ee0 = ee_s[gc], ee1 = ee_s[gc + 1];
            float d00 = zzr[0] + ee0 - 2.f * acc[tn][0];
            float d01 = zzr[0] + ee1 - 2.f * acc[tn][1];
            float d10 = zzr[1] + ee0 - 2.f * acc[tn][2];
            float d11 = zzr[1] + ee1 - 2.f * acc[tn][3];

            osm_upd(osm_m[0], osm_s[0], osm_i[0], d00, gc,     C);
            osm_upd(osm_m[0], osm_s[0], osm_i[0], d01, gc + 1, C);
            osm_upd(osm_m[1], osm_s[1], osm_i[1], d10, gc,     C);
            osm_upd(osm_m[1], osm_s[1], osm_i[1], d11, gc + 1, C);

            float* p0 = out + OFF_SA + (size_t)(brow + r0) * K_CODES + gc;
            float* p1 = out + OFF_SA + (size_t)(brow + r0 + 8) * K_CODES + gc;
            p0[0] = d00; p0[1] = d01;
            p1[0] = d10; p1[1] = d11;
        }
    }

    // ---- merge online states: lanes (xor 1,2) then across the two warp-halves
#pragma unroll
    for (int sl = 0; sl < 2; sl++) {
        float m = osm_m[sl], s = osm_s[sl]; int i = osm_i[sl];
#pragma unroll
        for (int off = 1; off <= 2; off <<= 1) {
            float om = __shfl_xor_sync(0xffffffffu, m, off);
            float os = __shfl_xor_sync(0xffffffffu, s, off);
            int   oi = __shfl_xor_sync(0xffffffffu, i, off);
            osm_merge(m, s, i, om, os, oi, C);
        }
        if ((lane & 3) == 0) {
            int row = wm * 16 + g + sl * 8;
            pm[row * 2 + wn] = m; ps[row * 2 + wn] = s; pi[row * 2 + wn] = i;
        }
    }
    __syncthreads();
    if (tid < BM) {
        float m = pm[tid * 2], s = ps[tid * 2]; int i = pi[tid * 2];
        osm_merge(m, s, i, pm[tid * 2 + 1], ps[tid * 2 + 1], pi[tid * 2 + 1], C);
        fm[tid] = m; fs[tid] = s; fi[tid] = i;
    }
    __syncthreads();

    // ---- Phase B: single-pass softmax normalize + z_q + commitment + segsums
    float commit_acc = 0.f;
    for (int rr = 0; rr < 8; rr++) {
        int row = w * 8 + rr;
        float dmin = fm[row];
        float invs = 1.0f / fs[row];
        int   code = fi[row];
        int grow = brow + row;

        float* sarow = out + OFF_SA + (size_t)grow * K_CODES;
#pragma unroll 4
        for (int it = 0; it < 32; it++) {
            int i = lane + it * 32;
            float d = sarow[i];
            float t = (dmin - d) * C;
            // outputs below 2^-126 underflow in fp32 anyway -> skip the MUFU
            float p = (t > -126.f) ? ex2(t) * invs : 0.f;
            sarow[i] = p;
        }

        const float* erow = embed + (size_t)code * D_DIM;
        const float* zrow = z + (size_t)grow * D_DIM;
        float* zqrow = out + OFF_ZQ + (size_t)grow * D_DIM;
        float* esrow = g_esum + (size_t)code * D_DIM;
#pragma unroll
        for (int it = 0; it < 8; it++) {
            int d = lane + it * 32;
            float ev = erow[d];
            float zv = zrow[d];
            zqrow[d] = ev;
            float df = zv - ev;
            commit_acc += df * df;
            atomicAdd(&esrow[d], zv);
        }
        if (lane == 0) {
            atomicAdd(&g_counts[code], 1.0f);
            out[OFF_CODES + grow] = (float)code;
        }
    }
#pragma unroll
    for (int o = 16; o; o >>= 1) commit_acc += __shfl_xor_sync(0xffffffffu, commit_acc, o);
    if (lane == 0) red[w] = commit_acc;
    __syncthreads();
    if (tid == 0) {
        float t = 0.f;
        for (int i = 0; i < 8; i++) t += red[i];
        atomicAdd(&g_commit, t);
    }
}

// ---------------------------------------------------------------------------
__global__ void __launch_bounds__(1024) ema_kernel(const float* __restrict__ cs,
                                                   float* __restrict__ out) {
    __shared__ float sh[33];
    int t = threadIdx.x, lane = t & 31, wid = t >> 5;

    float cnt = g_counts[t];
    float ncs = 0.99f * cs[t] + 0.01f * cnt;
    out[OFF_CS + t] = ncs;

    float v = ncs;
#pragma unroll
    for (int o = 16; o; o >>= 1) v += __shfl_xor_sync(0xffffffffu, v, o);
    if (lane == 0) sh[wid] = v;
    __syncthreads();
    if (t < 32) {
        float r = sh[t];
#pragma unroll
        for (int o = 16; o; o >>= 1) r += __shfl_xor_sync(0xffffffffu, r, o);
        if (t == 0) sh[32] = r;
    }
    __syncthreads();
    float n = sh[32];
    __syncthreads();

    float avg = cnt * (1.0f / (float)N_TOK);
    float term = -avg * logf(avg + 1e-10f);
    v = term;
#pragma unroll
    for (int o = 16; o; o >>= 1) v += __shfl_xor_sync(0xffffffffu, v, o);
    if (lane == 0) sh[wid] = v;
    __syncthreads();
    if (t < 32) {
        float r = sh[t];
#pragma unroll
        for (int o = 16; o; o >>= 1) r += __shfl_xor_sync(0xffffffffu, r, o);
        if (t == 0) {
            out[OFF_ENT]  = r;
            out[OFF_PERP] = expf(r);
            out[OFF_LOSS] = g_commit * (1.0f / 8388608.0f);
        }
    }
    float csn = (ncs + 1e-5f) / (n + 1024.0f * 1e-5f) * n;
    g_invcs[t] = 1.0f / csn;
}

__global__ void __launch_bounds__(1024) embed_update_kernel(const float* __restrict__ ea,
                                                            float* __restrict__ out) {
    int i = blockIdx.x * 1024 + threadIdx.x;
    float v = 0.99f * ea[i] + 0.01f * g_esum[i];
    out[OFF_EA + i] = v;
    out[OFF_EMBED + i] = v * g_invcs[i >> 8];
}

// ---------------------------------------------------------------------------
extern "C" void kernel_launch(void* const* d_in, const int* in_sizes, int n_in,
                              void* d_out, int out_size) {
    const float* z     = (const float*)d_in[0];
    const float* embed = (const float*)d_in[1];
    const float* cs    = (const float*)d_in[2];
    const float* ea    = (const float*)d_in[3];
    float* out = (float*)d_out;

    cudaFuncSetAttribute(dist_kernel, cudaFuncAttributeMaxDynamicSharedMemorySize, SMEM_BYTES);

    embed_prep_kernel<<<128, 256>>>(embed);
    dist_kernel<<<N_TOK / BM, 256, SMEM_BYTES>>>(z, embed, out);
    ema_kernel<<<1, 1024>>>(cs, out);
    embed_update_kernel<<<256, 1024>>>(ea, out);
    (void)in_sizes; (void)n_in; (void)out_size;
}

// round 15
// speedup vs baseline: 1.3491x; 1.3491x over previous
#include <cuda_runtime.h>
#include <cuda_bf16.h>
#include <cstdint>

#define N_TOK   32768
#define K_CODES 1024
#define D_DIM   256
#define BM      64

// Output layout: reference tuple concatenated as float32 in return order.
#define OFF_ZQ    0ull
#define OFF_CODES 8388608ull
#define OFF_LOSS  8421376ull
#define OFF_PERP  8421377ull
#define OFF_ENT   8421378ull
#define OFF_SA    8421379ull
#define OFF_EMBED 41975811ull
#define OFF_CS    42237955ull
#define OFF_EA    42238979ull

// ---------------------------------------------------------------------------
// Scratch (__device__ globals; no runtime allocation allowed)
__device__ float g_esum[K_CODES * D_DIM];
__device__ float g_counts[K_CODES];
__device__ float g_commit;
__device__ float g_ee[K_CODES];
__device__ float g_invcs[K_CODES];
__device__ __align__(16) unsigned short g_eh[K_CODES * D_DIM];  // embed bf16 hi
__device__ __align__(16) unsigned short g_el[K_CODES * D_DIM];  // embed bf16 lo

// ---------------------------------------------------------------------------
__device__ __forceinline__ uint32_t smem_u32(const void* p) {
    uint32_t a;
    asm("{ .reg .u64 t; cvta.to.shared.u64 t, %1; cvt.u32.u64 %0, t; }" : "=r"(a) : "l"(p));
    return a;
}
__device__ __forceinline__ float ex2(float x) {
    float r; asm("ex2.approx.ftz.f32 %0, %1;" : "=f"(r) : "f"(x)); return r;
}
#define SWZ(o) ((o) ^ (((o) >> 3) & 0x70u))

#define LDSM4(r, a) \
    asm volatile("ldmatrix.sync.aligned.m8n8.x4.shared.b16 {%0,%1,%2,%3}, [%4];" \
        : "=r"((r)[0]), "=r"((r)[1]), "=r"((r)[2]), "=r"((r)[3]) : "r"(a))
#define MMA16816(d, a, b) \
    asm volatile("mma.sync.aligned.m16n8k16.row.col.f32.bf16.bf16.f32 " \
        "{%0,%1,%2,%3},{%4,%5,%6,%7},{%8,%9},{%0,%1,%2,%3};" \
        : "+f"((d)[0]), "+f"((d)[1]), "+f"((d)[2]), "+f"((d)[3]) \
        : "r"((a)[0]), "r"((a)[1]), "r"((a)[2]), "r"((a)[3]), "r"((b)[0]), "r"((b)[1]))

#define CP_ASYNC16(saddr, gptr) \
    asm volatile("cp.async.cg.shared.global [%0], [%1], 16;" :: "r"(saddr), "l"(gptr))
#define CP_COMMIT() asm volatile("cp.async.commit_group;" ::: "memory")
#define CP_WAIT(n)  asm volatile("cp.async.wait_group %0;" :: "n"(n) : "memory")

__device__ __forceinline__ unsigned short f2bf(float v) {
    __nv_bfloat16 b = __float2bfloat16(v);
    return *reinterpret_cast<unsigned short*>(&b);
}
__device__ __forceinline__ float bf2f(unsigned short u) {
    __nv_bfloat16 b = *reinterpret_cast<__nv_bfloat16*>(&u);
    return __bfloat162float(b);
}

// ---------------------------------------------------------------------------
// embed prep: zero scratch + bf16 hi/lo split + squared norms. One warp/code.
__global__ void __launch_bounds__(256) embed_prep_kernel(const float* __restrict__ embed) {
    int gid = blockIdx.x * 256 + threadIdx.x;   // 0..32767
#pragma unroll
    for (int k = 0; k < 8; k++) g_esum[gid + k * 32768] = 0.f;
    if (gid < K_CODES) g_counts[gid] = 0.f;
    if (gid == 0) g_commit = 0.f;

    int w = threadIdx.x >> 5, lane = threadIdx.x & 31;
    int k = blockIdx.x * 8 + w;
    const float* e = embed + (size_t)k * D_DIM;
    float s = 0.f;
#pragma unroll
    for (int j = 0; j < 8; j++) {
        int d = lane + 32 * j;
        float v = e[d];
        unsigned short h = f2bf(v);
        unsigned short l = f2bf(v - bf2f(h));
        g_eh[k * D_DIM + d] = h;
        g_el[k * D_DIM + d] = l;
        s += v * v;
    }
#pragma unroll
    for (int o = 16; o; o >>= 1) s += __shfl_xor_sync(0xffffffffu, s, o);
    if (lane == 0) g_ee[k] = s;
}

// ---------------------------------------------------------------------------
// SMEM layout (bytes) — total 105088 -> 2 CTAs/SM
#define SM_RED  0u
#define SM_ZZ   64u
#define SM_PM   320u
#define SM_PI   1344u
#define SM_FM   1856u
#define SM_FI   2368u
#define SM_EE   2624u
#define SM_Z    6784u
#define SM_E    72320u
#define SMEM_BYTES 105088u

// async copy of E chunk L (nt = L>>2, c = L&3): 64 codes x 64 d, hi+lo = 16 KB
__device__ __forceinline__ void copy_chunk(uint32_t sb, int L, int tid) {
    int nt = L >> 2, c = L & 3;
    uint32_t dstb = SM_E + (uint32_t)(L & 1) * 16384u;
#pragma unroll
    for (int m = 0; m < 4; m++) {
        int linear = m * 256 + tid;          // 0..1023
        int s = linear >> 9, rem = linear & 511;
        int i = rem >> 3, grp = rem & 7;
        const unsigned short* src = s ? g_el : g_eh;
        const void* gp = (const void*)(src + ((size_t)(nt * 64 + i) * D_DIM + c * 64 + grp * 8));
        uint32_t off = SWZ((uint32_t)(i * 128 + grp * 16));
        CP_ASYNC16(sb + dstb + (uint32_t)s * 8192u + off, gp);
    }
}

__global__ void __launch_bounds__(256, 2) dist_kernel(
    const float* __restrict__ z, const float* __restrict__ embed,
    float* __restrict__ out)
{
    extern __shared__ char smem[];
    const uint32_t sb = smem_u32(smem);
    const int tid = threadIdx.x;
    const int w = tid >> 5, lane = tid & 31;
    const int wm = w & 3, wn = w >> 2;        // warp grid 4 (M) x 2 (N)
    const int brow = blockIdx.x * BM;
    const float C = 14.4269504088896341f;      // 10 / ln(2)

    float* red  = (float*)(smem + SM_RED);
    float* zz   = (float*)(smem + SM_ZZ);
    float* ee_s = (float*)(smem + SM_EE);
    float* pm   = (float*)(smem + SM_PM);
    int*   pi   = (int*)  (smem + SM_PI);
    float* fm   = (float*)(smem + SM_FM);
    int*   fi   = (int*)  (smem + SM_FI);

    if (tid < BM) zz[tid] = 0.f;
    __syncthreads();

    // kick off E chunk 0 fetch; overlaps z-tile load/split
    copy_chunk(sb, 0, tid);
    CP_COMMIT();

    // ---- load z tile [64 x 256] -> bf16 hi/lo split, swizzled smem, row norms
    {
        int r = tid >> 2, q = tid & 3;       // 4 threads per row, 64 d each
        float s = 0.f;
#pragma unroll
        for (int j = 0; j < 8; j++) {
            int d = q * 64 + j * 8;
            const float4* zp = (const float4*)(z + (size_t)(brow + r) * D_DIM + d);
            float4 a = zp[0], b = zp[1];
            float f[8] = {a.x, a.y, a.z, a.w, b.x, b.y, b.z, b.w};
            uint32_t hv[4], lv[4];
#pragma unroll
            for (int p = 0; p < 4; p++) {
                unsigned short h0 = f2bf(f[2*p]),   h1 = f2bf(f[2*p+1]);
                unsigned short l0 = f2bf(f[2*p]   - bf2f(h0));
                unsigned short l1 = f2bf(f[2*p+1] - bf2f(h1));
                hv[p] = (uint32_t)h0 | ((uint32_t)h1 << 16);
                lv[p] = (uint32_t)l0 | ((uint32_t)l1 << 16);
                s += f[2*p]*f[2*p] + f[2*p+1]*f[2*p+1];
            }
            int col = j * 8;
            uint32_t off = SWZ((uint32_t)(r * 128 + col * 2));
            *(uint4*)(smem + SM_Z + (0 + q) * 8192 + off) = make_uint4(hv[0],hv[1],hv[2],hv[3]);
            *(uint4*)(smem + SM_Z + (4 + q) * 8192 + off) = make_uint4(lv[0],lv[1],lv[2],lv[3]);
        }
        atomicAdd(&zz[r], s);
    }
    // preload ALL code norms once (1024 floats)
#pragma unroll
    for (int k = 0; k < 4; k++) ee_s[tid + k * 256] = g_ee[tid + k * 256];
    __syncthreads();

    const int g  = lane >> 2;           // fragment row-in-8
    const int t2 = (lane & 3) * 2;      // fragment col pair
    float zzr[2];
    zzr[0] = zz[wm * 16 + g];
    zzr[1] = zz[wm * 16 + g + 8];

    // running min/argmin per owned row-slot (rows wm*16+g, +8)
    float minv[2] = {3.4e38f, 3.4e38f};
    int   mini[2] = {0, 0};

    for (int nt = 0; nt < 16; nt++) {
        float acc[4][4];
#pragma unroll
        for (int tn = 0; tn < 4; tn++)
#pragma unroll
            for (int q = 0; q < 4; q++) acc[tn][q] = 0.f;

        for (int c = 0; c < 4; c++) {
            const int L = nt * 4 + c;
            CP_WAIT(0);          // copy L (sole outstanding group) complete
            __syncthreads();     // all warps past prior MMA; buffer (L+1)&1 free
            if (L + 1 < 64) {
                copy_chunk(sb, L + 1, tid);   // overlaps this chunk's MMAs
                CP_COMMIT();
            }

            const uint32_t eb = SM_E + (uint32_t)(L & 1) * 16384u;
#pragma unroll
            for (int ks = 0; ks < 4; ks++) {
                uint32_t ah[4], al[4];
                {
                    int row = wm * 16 + (lane & 15);
                    uint32_t kg = (uint32_t)(ks * 2 + (lane >> 4));
                    uint32_t boff = (uint32_t)(row * 128) + ((kg ^ (row & 7)) << 4);
                    LDSM4(ah, sb + SM_Z + (0 + c) * 8192 + boff);
                    LDSM4(al, sb + SM_Z + (4 + c) * 8192 + boff);
                }
                uint32_t bh[4][2], bl[4][2];
#pragma unroll
                for (int jp = 0; jp < 2; jp++) {
                    int mi = lane >> 3;
                    int row = wn * 32 + (jp * 2 + (mi >> 1)) * 8 + (lane & 7);
                    uint32_t kg = (uint32_t)(ks * 2 + (mi & 1));
                    uint32_t boff = (uint32_t)(row * 128) + ((kg ^ (row & 7)) << 4);
                    uint32_t q[4];
                    LDSM4(q, sb + eb + boff);
                    bh[jp*2+0][0] = q[0]; bh[jp*2+0][1] = q[1];
                    bh[jp*2+1][0] = q[2]; bh[jp*2+1][1] = q[3];
                    LDSM4(q, sb + eb + 8192u + boff);
                    bl[jp*2+0][0] = q[0]; bl[jp*2+0][1] = q[1];
                    bl[jp*2+1][0] = q[2]; bl[jp*2+1][1] = q[3];
                }
#pragma unroll
                for (int j = 0; j < 4; j++) MMA16816(acc[j], ah, bh[j]);
#pragma unroll
                for (int j = 0; j < 4; j++) MMA16816(acc[j], ah, bl[j]);
#pragma unroll
                for (int j = 0; j < 4; j++) MMA16816(acc[j], al, bh[j]);
            }
        }

        // ---- epilogue: dist, min/argmin tracking, scalar STG of raw dist
        // (OFF_SA is an ODD float offset -> rows only 4B-aligned)
        int r0 = wm * 16 + g;
#pragma unroll
        for (int tn = 0; tn < 4; tn++) {
            int col = wn * 32 + tn * 8 + t2;
            int gc  = nt * 64 + col;
            float ee0 = ee_s[gc], ee1 = ee_s[gc + 1];
            float d00 = zzr[0] + ee0 - 2.f * acc[tn][0];
            float d01 = zzr[0] + ee1 - 2.f * acc[tn][1];
            float d10 = zzr[1] + ee0 - 2.f * acc[tn][2];
            float d11 = zzr[1] + ee1 - 2.f * acc[tn][3];

            if (d00 < minv[0]) { minv[0] = d00; mini[0] = gc; }
            if (d01 < minv[0]) { minv[0] = d01; mini[0] = gc + 1; }
            if (d10 < minv[1]) { minv[1] = d10; mini[1] = gc; }
            if (d11 < minv[1]) { minv[1] = d11; mini[1] = gc + 1; }

            float* p0 = out + OFF_SA + (size_t)(brow + r0) * K_CODES + gc;
            float* p1 = out + OFF_SA + (size_t)(brow + r0 + 8) * K_CODES + gc;
            p0[0] = d00; p0[1] = d01;
            p1[0] = d10; p1[1] = d11;
        }
    }

    // ---- merge min/argmin: lanes (xor 1,2) then across the two warp-halves
#pragma unroll
    for (int sl = 0; sl < 2; sl++) {
        float m = minv[sl]; int i = mini[sl];
#pragma unroll
        for (int off = 1; off <= 2; off <<= 1) {
            float om = __shfl_xor_sync(0xffffffffu, m, off);
            int   oi = __shfl_xor_sync(0xffffffffu, i, off);
            if (om < m || (om == m && oi < i)) { m = om; i = oi; }
        }
        if ((lane & 3) == 0) {
            int row = wm * 16 + g + sl * 8;
            pm[row * 2 + wn] = m; pi[row * 2 + wn] = i;
        }
    }
    __syncthreads();
    if (tid < BM) {
        float m0 = pm[tid * 2], m1 = pm[tid * 2 + 1];
        int   i0 = pi[tid * 2], i1 = pi[tid * 2 + 1];
        if (m1 < m0 || (m1 == m0 && i1 < i0)) { m0 = m1; i0 = i1; }
        fm[tid] = m0; fi[tid] = i0;
    }
    __syncthreads();

    // ---- Phase B: two-pass softmax (sum then scale) + z_q + commit + segsums
    float commit_acc = 0.f;
    for (int rr = 0; rr < 8; rr++) {
        int row = w * 8 + rr;
        float dmin = fm[row];
        int   code = fi[row];
        int grow = brow + row;

        float* sarow = out + OFF_SA + (size_t)grow * K_CODES;
        float s = 0.f;
#pragma unroll 4
        for (int it = 0; it < 32; it++) {
            int i = lane + it * 32;
            float p = ex2((dmin - sarow[i]) * C);
            s += p;
            sarow[i] = p;                       // unnormalized
        }
#pragma unroll
        for (int o = 16; o; o >>= 1) s += __shfl_xor_sync(0xffffffffu, s, o);
        float invs = 1.0f / s;
#pragma unroll 4
        for (int it = 0; it < 32; it++) {
            int i = lane + it * 32;
            sarow[i] *= invs;
        }

        const float* erow = embed + (size_t)code * D_DIM;
        const float* zrow = z + (size_t)grow * D_DIM;
        float* zqrow = out + OFF_ZQ + (size_t)grow * D_DIM;
        float* esrow = g_esum + (size_t)code * D_DIM;
#pragma unroll
        for (int it = 0; it < 8; it++) {
            int d = lane + it * 32;
            float ev = erow[d];
            float zv = zrow[d];
            zqrow[d] = ev;
            float df = zv - ev;
            commit_acc += df * df;
            atomicAdd(&esrow[d], zv);
        }
        if (lane == 0) {
            atomicAdd(&g_counts[code], 1.0f);
            out[OFF_CODES + grow] = (float)code;
        }
    }
#pragma unroll
    for (int o = 16; o; o >>= 1) commit_acc += __shfl_xor_sync(0xffffffffu, commit_acc, o);
    if (lane == 0) red[w] = commit_acc;
    __syncthreads();
    if (tid == 0) {
        float t = 0.f;
        for (int i = 0; i < 8; i++) t += red[i];
        atomicAdd(&g_commit, t);
    }
}

// ---------------------------------------------------------------------------
__global__ void __launch_bounds__(1024) ema_kernel(const float* __restrict__ cs,
                                                   float* __restrict__ out) {
    __shared__ float sh[33];
    int t = threadIdx.x, lane = t & 31, wid = t >> 5;

    float cnt = g_counts[t];
    float ncs = 0.99f * cs[t] + 0.01f * cnt;
    out[OFF_CS + t] = ncs;

    float v = ncs;
#pragma unroll
    for (int o = 16; o; o >>= 1) v += __shfl_xor_sync(0xffffffffu, v, o);
    if (lane == 0) sh[wid] = v;
    __syncthreads();
    if (t < 32) {
        float r = sh[t];
#pragma unroll
        for (int o = 16; o; o >>= 1) r += __shfl_xor_sync(0xffffffffu, r, o);
        if (t == 0) sh[32] = r;
    }
    __syncthreads();
    float n = sh[32];
    __syncthreads();

    float avg = cnt * (1.0f / (float)N_TOK);
    float term = -avg * logf(avg + 1e-10f);
    v = term;
#pragma unroll
    for (int o = 16; o; o >>= 1) v += __shfl_xor_sync(0xffffffffu, v, o);
    if (lane == 0) sh[wid] = v;
    __syncthreads();
    if (t < 32) {
        float r = sh[t];
#pragma unroll
        for (int o = 16; o; o >>= 1) r += __shfl_xor_sync(0xffffffffu, r, o);
        if (t == 0) {
            out[OFF_ENT]  = r;
            out[OFF_PERP] = expf(r);
            out[OFF_LOSS] = g_commit * (1.0f / 8388608.0f);
        }
    }
    float csn = (ncs + 1e-5f) / (n + 1024.0f * 1e-5f) * n;
    g_invcs[t] = 1.0f / csn;
}

__global__ void __launch_bounds__(1024) embed_update_kernel(const float* __restrict__ ea,
                                                            float* __restrict__ out) {
    int i = blockIdx.x * 1024 + threadIdx.x;
    float v = 0.99f * ea[i] + 0.01f * g_esum[i];
    out[OFF_EA + i] = v;
    out[OFF_EMBED + i] = v * g_invcs[i >> 8];
}

// ---------------------------------------------------------------------------
extern "C" void kernel_launch(void* const* d_in, const int* in_sizes, int n_in,
                              void* d_out, int out_size) {
    const float* z     = (const float*)d_in[0];
    const float* embed = (const float*)d_in[1];
    const float* cs    = (const float*)d_in[2];
    const float* ea    = (const float*)d_in[3];
    float* out = (float*)d_out;

    cudaFuncSetAttribute(dist_kernel, cudaFuncAttributeMaxDynamicSharedMemorySize, SMEM_BYTES);

    embed_prep_kernel<<<128, 256>>>(embed);
    dist_kernel<<<N_TOK / BM, 256, SMEM_BYTES>>>(z, embed, out);
    ema_kernel<<<1, 1024>>>(cs, out);
    embed_update_kernel<<<256, 1024>>>(ea, out);
    (void)in_sizes; (void)n_in; (void)out_size;
}

// round 16
// speedup vs baseline: 1.5001x; 1.1119x over previous
#include <cuda_runtime.h>
#include <cuda_bf16.h>
#include <cstdint>

#define N_TOK   32768
#define K_CODES 1024
#define D_DIM   256
#define BM      64

// Output layout: reference tuple concatenated as float32 in return order.
#define OFF_ZQ    0ull
#define OFF_CODES 8388608ull
#define OFF_LOSS  8421376ull
#define OFF_PERP  8421377ull
#define OFF_ENT   8421378ull
#define OFF_SA    8421379ull
#define OFF_EMBED 41975811ull
#define OFF_CS    42237955ull
#define OFF_EA    42238979ull

// ---------------------------------------------------------------------------
// Scratch (__device__ globals; no runtime allocation allowed)
__device__ float g_esum[K_CODES * D_DIM];
__device__ float g_counts[K_CODES];
__device__ float g_commit;
__device__ float g_ee[K_CODES];
__device__ __align__(16) unsigned short g_eh[K_CODES * D_DIM];  // embed bf16 hi
__device__ __align__(16) unsigned short g_el[K_CODES * D_DIM];  // embed bf16 lo

// ---------------------------------------------------------------------------
__device__ __forceinline__ uint32_t smem_u32(const void* p) {
    uint32_t a;
    asm("{ .reg .u64 t; cvta.to.shared.u64 t, %1; cvt.u32.u64 %0, t; }" : "=r"(a) : "l"(p));
    return a;
}
__device__ __forceinline__ float ex2(float x) {
    float r; asm("ex2.approx.ftz.f32 %0, %1;" : "=f"(r) : "f"(x)); return r;
}
#define SWZ(o) ((o) ^ (((o) >> 3) & 0x70u))

#define LDSM4(r, a) \
    asm volatile("ldmatrix.sync.aligned.m8n8.x4.shared.b16 {%0,%1,%2,%3}, [%4];" \
        : "=r"((r)[0]), "=r"((r)[1]), "=r"((r)[2]), "=r"((r)[3]) : "r"(a))
#define MMA16816(d, a, b) \
    asm volatile("mma.sync.aligned.m16n8k16.row.col.f32.bf16.bf16.f32 " \
        "{%0,%1,%2,%3},{%4,%5,%6,%7},{%8,%9},{%0,%1,%2,%3};" \
        : "+f"((d)[0]), "+f"((d)[1]), "+f"((d)[2]), "+f"((d)[3]) \
        : "r"((a)[0]), "r"((a)[1]), "r"((a)[2]), "r"((a)[3]), "r"((b)[0]), "r"((b)[1]))

#define CP_ASYNC16(saddr, gptr) \
    asm volatile("cp.async.cg.shared.global [%0], [%1], 16;" :: "r"(saddr), "l"(gptr))
#define CP_COMMIT() asm volatile("cp.async.commit_group;" ::: "memory")
#define CP_WAIT(n)  asm volatile("cp.async.wait_group %0;" :: "n"(n) : "memory")

__device__ __forceinline__ unsigned short f2bf(float v) {
    __nv_bfloat16 b = __float2bfloat16(v);
    return *reinterpret_cast<unsigned short*>(&b);
}
__device__ __forceinline__ float bf2f(unsigned short u) {
    __nv_bfloat16 b = *reinterpret_cast<__nv_bfloat16*>(&u);
    return __bfloat162float(b);
}

// ---------------------------------------------------------------------------
// embed prep: zero scratch + bf16 hi/lo split + squared norms. One warp/code.
__global__ void __launch_bounds__(256) embed_prep_kernel(const float* __restrict__ embed) {
    int gid = blockIdx.x * 256 + threadIdx.x;   // 0..32767
#pragma unroll
    for (int k = 0; k < 8; k++) g_esum[gid + k * 32768] = 0.f;
    if (gid < K_CODES) g_counts[gid] = 0.f;
    if (gid == 0) g_commit = 0.f;

    int w = threadIdx.x >> 5, lane = threadIdx.x & 31;
    int k = blockIdx.x * 8 + w;
    const float* e = embed + (size_t)k * D_DIM;
    float s = 0.f;
#pragma unroll
    for (int j = 0; j < 8; j++) {
        int d = lane + 32 * j;
        float v = e[d];
        unsigned short h = f2bf(v);
        unsigned short l = f2bf(v - bf2f(h));
        g_eh[k * D_DIM + d] = h;
        g_el[k * D_DIM + d] = l;
        s += v * v;
    }
#pragma unroll
    for (int o = 16; o; o >>= 1) s += __shfl_xor_sync(0xffffffffu, s, o);
    if (lane == 0) g_ee[k] = s;
}

// ---------------------------------------------------------------------------
// SMEM layout (bytes) — total 105088 -> 2 CTAs/SM
#define SM_RED  0u
#define SM_ZZ   64u
#define SM_PM   320u
#define SM_PS   832u
#define SM_PI   1344u
#define SM_FM   1856u
#define SM_FS   2112u
#define SM_FI   2368u
#define SM_EE   2624u
#define SM_Z    6784u
#define SM_E    72320u
#define SMEM_BYTES 105088u

// merge two online-softmax states
__device__ __forceinline__ void osm_merge(float& m, float& s, int& i,
                                          float om, float os, int oi, float C) {
    if (om < m || (om == m && oi < i)) {
        s = os + s * ex2((om - m) * C);
        m = om; i = oi;
    } else {
        s = s + os * ex2((m - om) * C);
    }
}

// async copy of E chunk L (nt = L>>2, c = L&3): 64 codes x 64 d, hi+lo = 16 KB
__device__ __forceinline__ void copy_chunk(uint32_t sb, int L, int tid) {
    int nt = L >> 2, c = L & 3;
    uint32_t dstb = SM_E + (uint32_t)(L & 1) * 16384u;
#pragma unroll
    for (int m = 0; m < 4; m++) {
        int linear = m * 256 + tid;          // 0..1023
        int s = linear >> 9, rem = linear & 511;
        int i = rem >> 3, grp = rem & 7;
        const unsigned short* src = s ? g_el : g_eh;
        const void* gp = (const void*)(src + ((size_t)(nt * 64 + i) * D_DIM + c * 64 + grp * 8));
        uint32_t off = SWZ((uint32_t)(i * 128 + grp * 16));
        CP_ASYNC16(sb + dstb + (uint32_t)s * 8192u + off, gp);
    }
}

__global__ void __launch_bounds__(256, 2) dist_kernel(
    const float* __restrict__ z, const float* __restrict__ embed,
    float* __restrict__ out)
{
    extern __shared__ char smem[];
    const uint32_t sb = smem_u32(smem);
    const int tid = threadIdx.x;
    const int w = tid >> 5, lane = tid & 31;
    const int wm = w & 3, wn = w >> 2;        // warp grid 4 (M) x 2 (N)
    const int brow = blockIdx.x * BM;
    const float C = 14.4269504088896341f;      // 10 / ln(2)

    float* red  = (float*)(smem + SM_RED);
    float* zz   = (float*)(smem + SM_ZZ);
    float* ee_s = (float*)(smem + SM_EE);
    float* pm   = (float*)(smem + SM_PM);
    float* ps   = (float*)(smem + SM_PS);
    int*   pi   = (int*)  (smem + SM_PI);
    float* fm   = (float*)(smem + SM_FM);
    float* fs   = (float*)(smem + SM_FS);
    int*   fi   = (int*)  (smem + SM_FI);

    if (tid < BM) zz[tid] = 0.f;
    __syncthreads();

    // kick off E chunk 0 fetch; overlaps z-tile load/split
    copy_chunk(sb, 0, tid);
    CP_COMMIT();

    // ---- load z tile [64 x 256] -> bf16 hi/lo split, swizzled smem, row norms
    {
        int r = tid >> 2, q = tid & 3;       // 4 threads per row, 64 d each
        float s = 0.f;
#pragma unroll
        for (int j = 0; j < 8; j++) {
            int d = q * 64 + j * 8;
            const float4* zp = (const float4*)(z + (size_t)(brow + r) * D_DIM + d);
            float4 a = zp[0], b = zp[1];
            float f[8] = {a.x, a.y, a.z, a.w, b.x, b.y, b.z, b.w};
            uint32_t hv[4], lv[4];
#pragma unroll
            for (int p = 0; p < 4; p++) {
                unsigned short h0 = f2bf(f[2*p]),   h1 = f2bf(f[2*p+1]);
                unsigned short l0 = f2bf(f[2*p]   - bf2f(h0));
                unsigned short l1 = f2bf(f[2*p+1] - bf2f(h1));
                hv[p] = (uint32_t)h0 | ((uint32_t)h1 << 16);
                lv[p] = (uint32_t)l0 | ((uint32_t)l1 << 16);
                s += f[2*p]*f[2*p] + f[2*p+1]*f[2*p+1];
            }
            int col = j * 8;
            uint32_t off = SWZ((uint32_t)(r * 128 + col * 2));
            *(uint4*)(smem + SM_Z + (0 + q) * 8192 + off) = make_uint4(hv[0],hv[1],hv[2],hv[3]);
            *(uint4*)(smem + SM_Z + (4 + q) * 8192 + off) = make_uint4(lv[0],lv[1],lv[2],lv[3]);
        }
        atomicAdd(&zz[r], s);
    }
    // preload ALL code norms once (1024 floats)
#pragma unroll
    for (int k = 0; k < 4; k++) ee_s[tid + k * 256] = g_ee[tid + k * 256];
    __syncthreads();

    const int g  = lane >> 2;           // fragment row-in-8
    const int t2 = (lane & 3) * 2;      // fragment col pair
    float zzr[2];
    zzr[0] = zz[wm * 16 + g];
    zzr[1] = zz[wm * 16 + g + 8];

    // online softmax state per owned row-slot (rows wm*16+g, +8)
    float osm_m[2] = {3.4e38f, 3.4e38f};
    float osm_s[2] = {0.f, 0.f};
    int   osm_i[2] = {0, 0};

    for (int nt = 0; nt < 16; nt++) {
        float acc[4][4];
#pragma unroll
        for (int tn = 0; tn < 4; tn++)
#pragma unroll
            for (int q = 0; q < 4; q++) acc[tn][q] = 0.f;

        for (int c = 0; c < 4; c++) {
            const int L = nt * 4 + c;
            CP_WAIT(0);          // copy L (sole outstanding group) complete
            __syncthreads();     // all warps past chunk L-1 MMA; data visible
            if (L + 1 < 64) {
                copy_chunk(sb, L + 1, tid);   // overlaps this chunk's MMAs
                CP_COMMIT();
            }

            const uint32_t eb = SM_E + (uint32_t)(L & 1) * 16384u;
#pragma unroll
            for (int ks = 0; ks < 4; ks++) {
                uint32_t ah[4], al[4];
                {
                    int row = wm * 16 + (lane & 15);
                    uint32_t kg = (uint32_t)(ks * 2 + (lane >> 4));
                    uint32_t boff = (uint32_t)(row * 128) + ((kg ^ (row & 7)) << 4);
                    LDSM4(ah, sb + SM_Z + (0 + c) * 8192 + boff);
                    LDSM4(al, sb + SM_Z + (4 + c) * 8192 + boff);
                }
                uint32_t bh[4][2], bl[4][2];
#pragma unroll
                for (int jp = 0; jp < 2; jp++) {
                    int mi = lane >> 3;
                    int row = wn * 32 + (jp * 2 + (mi >> 1)) * 8 + (lane & 7);
                    uint32_t kg = (uint32_t)(ks * 2 + (mi & 1));
                    uint32_t boff = (uint32_t)(row * 128) + ((kg ^ (row & 7)) << 4);
                    uint32_t q[4];
                    LDSM4(q, sb + eb + boff);
                    bh[jp*2+0][0] = q[0]; bh[jp*2+0][1] = q[1];
                    bh[jp*2+1][0] = q[2]; bh[jp*2+1][1] = q[3];
                    LDSM4(q, sb + eb + 8192u + boff);
                    bl[jp*2+0][0] = q[0]; bl[jp*2+0][1] = q[1];
                    bl[jp*2+1][0] = q[2]; bl[jp*2+1][1] = q[3];
                }
#pragma unroll
                for (int j = 0; j < 4; j++) MMA16816(acc[j], ah, bh[j]);
#pragma unroll
                for (int j = 0; j < 4; j++) MMA16816(acc[j], ah, bl[j]);
#pragma unroll
                for (int j = 0; j < 4; j++) MMA16816(acc[j], al, bh[j]);
            }
        }

        // ---- epilogue: dist, online softmax, scalar STG to sa slot
        // (OFF_SA is an ODD float offset -> rows only 4B-aligned)
        int r0 = wm * 16 + g;
#pragma unroll
        for (int tn = 0; tn < 4; tn++) {
            int col = wn * 32 + tn * 8 + t2;
            int gc  = nt * 64 + col;
            float ee0 = ee_s[gc], ee1 = ee_s[gc + 1];
            float d00 = zzr[0] + ee0 - 2.f * acc[tn][0];
            float d01 = zzr[0] + ee1 - 2.f * acc[tn][1];
            float d10 = zzr[1] + ee0 - 2.f * acc[tn][2];
            float d11 = zzr[1] + ee1 - 2.f * acc[tn][3];

            if (d00 < osm_m[0]) { osm_s[0] = osm_s[0] * ex2((d00 - osm_m[0]) * C) + 1.f; osm_m[0] = d00; osm_i[0] = gc; }
            else osm_s[0] += ex2((osm_m[0] - d00) * C);
            if (d01 < osm_m[0]) { osm_s[0] = osm_s[0] * ex2((d01 - osm_m[0]) * C) + 1.f; osm_m[0] = d01; osm_i[0] = gc + 1; }
            else osm_s[0] += ex2((osm_m[0] - d01) * C);
            if (d10 < osm_m[1]) { osm_s[1] = osm_s[1] * ex2((d10 - osm_m[1]) * C) + 1.f; osm_m[1] = d10; osm_i[1] = gc; }
            else osm_s[1] += ex2((osm_m[1] - d10) * C);
            if (d11 < osm_m[1]) { osm_s[1] = osm_s[1] * ex2((d11 - osm_m[1]) * C) + 1.f; osm_m[1] = d11; osm_i[1] = gc + 1; }
            else osm_s[1] += ex2((osm_m[1] - d11) * C);

            float* p0 = out + OFF_SA + (size_t)(brow + r0) * K_CODES + gc;
            float* p1 = out + OFF_SA + (size_t)(brow + r0 + 8) * K_CODES + gc;
            p0[0] = d00; p0[1] = d01;
            p1[0] = d10; p1[1] = d11;
        }
    }

    // ---- merge online states: lanes (xor 1,2) then across the two warp-halves
#pragma unroll
    for (int sl = 0; sl < 2; sl++) {
        float m = osm_m[sl], s = osm_s[sl]; int i = osm_i[sl];
#pragma unroll
        for (int off = 1; off <= 2; off <<= 1) {
            float om = __shfl_xor_sync(0xffffffffu, m, off);
            float os = __shfl_xor_sync(0xffffffffu, s, off);
            int   oi = __shfl_xor_sync(0xffffffffu, i, off);
            osm_merge(m, s, i, om, os, oi, C);
        }
        if ((lane & 3) == 0) {
            int row = wm * 16 + g + sl * 8;
            pm[row * 2 + wn] = m; ps[row * 2 + wn] = s; pi[row * 2 + wn] = i;
        }
    }
    __syncthreads();
    if (tid < BM) {
        float m = pm[tid * 2], s = ps[tid * 2]; int i = pi[tid * 2];
        osm_merge(m, s, i, pm[tid * 2 + 1], ps[tid * 2 + 1], pi[tid * 2 + 1], C);
        fm[tid] = m; fs[tid] = s; fi[tid] = i;
    }
    __syncthreads();

    // ---- Phase B: single-pass softmax normalize + z_q + commitment + segsums
    float commit_acc = 0.f;
    for (int rr = 0; rr < 8; rr++) {
        int row = w * 8 + rr;
        float dmin = fm[row];
        float invs = 1.0f / fs[row];
        int   code = fi[row];
        int grow = brow + row;

        float* sarow = out + OFF_SA + (size_t)grow * K_CODES;
#pragma unroll 4
        for (int it = 0; it < 32; it++) {
            int i = lane + it * 32;
            float d = sarow[i];
            sarow[i] = ex2((dmin - d) * C) * invs;
        }

        const float* erow = embed + (size_t)code * D_DIM;
        const float* zrow = z + (size_t)grow * D_DIM;
        float* zqrow = out + OFF_ZQ + (size_t)grow * D_DIM;
        float* esrow = g_esum + (size_t)code * D_DIM;
#pragma unroll
        for (int it = 0; it < 8; it++) {
            int d = lane + it * 32;
            float ev = erow[d];
            float zv = zrow[d];
            zqrow[d] = ev;
            float df = zv - ev;
            commit_acc += df * df;
            atomicAdd(&esrow[d], zv);
        }
        if (lane == 0) {
            atomicAdd(&g_counts[code], 1.0f);
            out[OFF_CODES + grow] = (float)code;
        }
    }
#pragma unroll
    for (int o = 16; o; o >>= 1) commit_acc += __shfl_xor_sync(0xffffffffu, commit_acc, o);
    if (lane == 0) red[w] = commit_acc;
    __syncthreads();
    if (tid == 0) {
        float t = 0.f;
        for (int i = 0; i < 8; i++) t += red[i];
        atomicAdd(&g_commit, t);
    }
}

// ---------------------------------------------------------------------------
// Merged tail: EMA scalars + entropy + embed update. 256 blocks x 1024 thr.
// Every block redundantly reduces n over all 1024 codes (L2-hot, cheap);
// block b owns codes [b*4, b*4+4) for CS/invcs, and 1024 embed elements.
__global__ void __launch_bounds__(1024) tail_kernel(const float* __restrict__ cs,
                                                    const float* __restrict__ ea,
                                                    float* __restrict__ out) {
    __shared__ float sh[33];
    __shared__ float s_inv[4];
    int t = threadIdx.x, lane = t & 31, wid = t >> 5;
    int b = blockIdx.x;

    float cnt = g_counts[t];
    float ncs = 0.99f * cs[t] + 0.01f * cnt;

    // n = sum(new_cluster_size) over all codes
    float v = ncs;
#pragma unroll
    for (int o = 16; o; o >>= 1) v += __shfl_xor_sync(0xffffffffu, v, o);
    if (lane == 0) sh[wid] = v;
    __syncthreads();
    if (t < 32) {
        float r = sh[t];
#pragma unroll
        for (int o = 16; o; o >>= 1) r += __shfl_xor_sync(0xffffffffu, r, o);
        if (t == 0) sh[32] = r;
    }
    __syncthreads();
    float n = sh[32];

    if (t < 4) {
        int k = b * 4 + t;
        float ncs_k = 0.99f * cs[k] + 0.01f * g_counts[k];
        out[OFF_CS + k] = ncs_k;
        float csn = (ncs_k + 1e-5f) / (n + 1024.0f * 1e-5f) * n;
        s_inv[t] = 1.0f / csn;
    }
    __syncthreads();      // sh reuse below + s_inv visibility

    // entropy reduction (all blocks compute; only block 0 writes scalars)
    float avg = cnt * (1.0f / (float)N_TOK);
    float term = -avg * logf(avg + 1e-10f);
    v = term;
#pragma unroll
    for (int o = 16; o; o >>= 1) v += __shfl_xor_sync(0xffffffffu, v, o);
    if (lane == 0) sh[wid] = v;
    __syncthreads();
    if (b == 0 && t < 32) {
        float r = sh[t];
#pragma unroll
        for (int o = 16; o; o >>= 1) r += __shfl_xor_sync(0xffffffffu, r, o);
        if (t == 0) {
            out[OFF_ENT]  = r;
            out[OFF_PERP] = expf(r);
            out[OFF_LOSS] = g_commit * (1.0f / 8388608.0f);
        }
    }

    // embed / embed_avg update: one element per thread
    int i = b * 1024 + t;
    float v2 = 0.99f * ea[i] + 0.01f * g_esum[i];
    out[OFF_EA + i] = v2;
    out[OFF_EMBED + i] = v2 * s_inv[t >> 8];
}

// ---------------------------------------------------------------------------
extern "C" void kernel_launch(void* const* d_in, const int* in_sizes, int n_in,
                              void* d_out, int out_size) {
    const float* z     = (const float*)d_in[0];
    const float* embed = (const float*)d_in[1];
    const float* cs    = (const float*)d_in[2];
    const float* ea    = (const float*)d_in[3];
    float* out = (float*)d_out;

    cudaFuncSetAttribute(dist_kernel, cudaFuncAttributeMaxDynamicSharedMemorySize, SMEM_BYTES);

    embed_prep_kernel<<<128, 256>>>(embed);
    dist_kernel<<<N_TOK / BM, 256, SMEM_BYTES>>>(z, embed, out);
    tail_kernel<<<256, 1024>>>(cs, ea, out);
    (void)in_sizes; (void)n_in; (void)out_size;
}